// round 16
// baseline (speedup 1.0000x reference)
#include <cuda_runtime.h>
#include <math.h>

// Problem constants
#define BSZ 32
#define SSZ 1024
#define DSZ 1024

typedef unsigned long long ull;

// Scratch buffers (device globals — no allocation allowed in kernel_launch).
__device__ float g_buf0[(size_t)BSZ * SSZ * DSZ];   // Z0 time-major [S][B][D]
__device__ float g_buf1[(size_t)BSZ * SSZ * DSZ];   // (unused; kept for gemm path)
// Paired h state per layer, double-buffered by parity:
// g_hpX[p][b][j] = (h[b][j], h[b][j+512])
__device__ float2 g_hp0[2][BSZ][DSZ / 2];
__device__ float2 g_hp1[2][BSZ][DSZ / 2];
// W1 transposed+paired: g_w1t[c][j] = (W1[j][c], W1[j+512][c])
__device__ float2 g_w1t[DSZ][DSZ / 2];

// Per-group wavefront counters (2 groups, separate 128B lines) + cleanup.
__device__ unsigned g_cnt[2 * 32];
__device__ unsigned g_cleanup;

// ---------------------------------------------------------------------------
// Packed f32x2 helpers (sm_100+). Each lane is an independent IEEE fp32 FMA.
// ---------------------------------------------------------------------------
__device__ __forceinline__ ull fma2(ull a, ull b, ull c) {
    ull d;
    asm("fma.rn.f32x2 %0, %1, %2, %3;" : "=l"(d) : "l"(a), "l"(b), "l"(c));
    return d;
}
__device__ __forceinline__ void unpack2(ull v, float& lo, float& hi) {
    asm("mov.b64 {%0, %1}, %2;" : "=f"(lo), "=f"(hi) : "l"(v));
}
__device__ __forceinline__ ull pack2(float lo, float hi) {
    ull r;
    asm("mov.b64 %0, {%1, %2};" : "=l"(r) : "f"(lo), "f"(hi));
    return r;
}

// ---------------------------------------------------------------------------
// Reference arithmetic (validated bit-exact rounds 9-14):
//   dot  = split-K=2: two ascending fp32 fmaf chains of 512, combined s0+s1
//   z    = (inp@W + h_prev@U) + b  (rn adds, that order)
//   tanh = XLA fast-tanh with_fma: clamp +-7.99881172180175781, FMA Horner.
// ---------------------------------------------------------------------------
__device__ __forceinline__ float xla_tanh(float x) {
    const float kMax = 7.99881172180175781f;
    float ax = fabsf(x);
    float xc = fminf(fmaxf(x, -kMax), kMax);
    float x2 = __fmul_rn(xc, xc);
    float p = -2.76076847742355e-16f;
    p = fmaf(x2, p, 2.00018790482477e-13f);
    p = fmaf(x2, p, -8.60467152213735e-11f);
    p = fmaf(x2, p, 5.12229709037114e-08f);
    p = fmaf(x2, p, 1.48572235717979e-05f);
    p = fmaf(x2, p, 6.37261928875436e-04f);
    p = fmaf(x2, p, 4.89352455891786e-03f);
    p = __fmul_rn(xc, p);
    float q = 1.19825839466702e-06f;
    q = fmaf(x2, q, 1.18534705686654e-04f);
    q = fmaf(x2, q, 2.26843463243900e-03f);
    q = fmaf(x2, q, 4.89352518554385e-03f);
    float r = __fdiv_rn(p, q);
    return (ax < 0.0004f) ? x : r;
}

// ---------------------------------------------------------------------------
// FFMA2 GEMM (validated): C = A @ W, split-K=2 chains in f32x2 lanes.
// Used only for Z0 = x @ W0 (remap=1 -> time-major).
// ---------------------------------------------------------------------------
__global__ __launch_bounds__(256) void gemm_kernel(
    const float* __restrict__ A_ext, int a_sel,
    const float* __restrict__ W,
    int c_sel, int remap)
{
    const int N_ = DSZ, K_ = DSZ;
    const float* A = (a_sel == 0) ? (const float*)g_buf0 : A_ext;
    float* C = (c_sel == 0) ? g_buf0 : g_buf1;

    __shared__ ull As2[8][132];
    __shared__ ull Bs2[8][66];

    const int tid = threadIdx.x;
    const int tx = tid & 15;
    const int ty = tid >> 4;
    const int m0 = blockIdx.y * 128;
    const int n0 = blockIdx.x * 64;

    ull acc2[8][4];
#pragma unroll
    for (int i = 0; i < 8; i++)
#pragma unroll
        for (int j = 0; j < 4; j++) acc2[i][j] = 0ull;

    const int arow = tid >> 1;
    const int akq = (tid & 1) * 4;
    const int brow = tid >> 4;
    const int bnq = (tid & 15) * 4;

    for (int kt = 0; kt < 512; kt += 8) {
        {
            float4 lo = *(const float4*)&A[(size_t)(m0 + arow) * K_ + kt + akq];
            float4 hi = *(const float4*)&A[(size_t)(m0 + arow) * K_ + kt + 512 + akq];
            As2[akq + 0][arow] = pack2(lo.x, hi.x);
            As2[akq + 1][arow] = pack2(lo.y, hi.y);
            As2[akq + 2][arow] = pack2(lo.z, hi.z);
            As2[akq + 3][arow] = pack2(lo.w, hi.w);
        }
        if (tid < 128) {
            float4 blo = *(const float4*)&W[(size_t)(kt + brow) * N_ + n0 + bnq];
            float4 bhi = *(const float4*)&W[(size_t)(kt + 512 + brow) * N_ + n0 + bnq];
            Bs2[brow][bnq + 0] = pack2(blo.x, bhi.x);
            Bs2[brow][bnq + 1] = pack2(blo.y, bhi.y);
            Bs2[brow][bnq + 2] = pack2(blo.z, bhi.z);
            Bs2[brow][bnq + 3] = pack2(blo.w, bhi.w);
        }
        __syncthreads();

#pragma unroll
        for (int kk = 0; kk < 8; kk++) {
            ull a2[8], b2[4];
#pragma unroll
            for (int i = 0; i < 8; i++) a2[i] = As2[kk][ty * 8 + i];
#pragma unroll
            for (int j = 0; j < 4; j++) b2[j] = Bs2[kk][tx * 4 + j];
#pragma unroll
            for (int i = 0; i < 8; i++)
#pragma unroll
                for (int j = 0; j < 4; j++)
                    acc2[i][j] = fma2(a2[i], b2[j], acc2[i][j]);
        }
        __syncthreads();
    }

#pragma unroll
    for (int i = 0; i < 8; i++) {
        int m = m0 + ty * 8 + i;
        int orow = remap ? ((m & (SSZ - 1)) * BSZ + (m >> 10)) : m;
        float lo, hi;
        float4 v;
        unpack2(acc2[i][0], lo, hi); v.x = __fadd_rn(lo, hi);
        unpack2(acc2[i][1], lo, hi); v.y = __fadd_rn(lo, hi);
        unpack2(acc2[i][2], lo, hi); v.z = __fadd_rn(lo, hi);
        unpack2(acc2[i][3], lo, hi); v.w = __fadd_rn(lo, hi);
        *(float4*)&C[(size_t)orow * N_ + n0 + tx * 4] = v;
    }
}

// ---------------------------------------------------------------------------
// W1 transpose+pair prep: g_w1t[c][j] = (W1[j][c], W1[j+512][c]).
// ---------------------------------------------------------------------------
__global__ __launch_bounds__(256) void transpose_w1(const float* __restrict__ W1)
{
    int idx = blockIdx.x * 256 + threadIdx.x;   // 0 .. 1024*512-1
    int c = idx & (DSZ - 1);
    int j = idx >> 10;                           // 0..511
    float2 v;
    v.x = W1[(size_t)j * DSZ + c];
    v.y = W1[(size_t)(j + 512) * DSZ + c];
    g_w1t[c][j] = v;
}

// ---------------------------------------------------------------------------
// Fused two-layer wavefront scan. Grid = 128 CTAs:
//   layer = bid>>6 (0/1), grp = (bid>>5)&1 (16 b-rows each), cslice = bid&31.
// Wavefront w (0..1024): L0 computes h0_w; L1 computes h1_{w-1} including
// the in-kernel zW1 = h0_{w-1} @ W1 (bit-exact split-K=2 chain, W1T from L2).
// One 64-CTA monotonic release/acquire barrier per group per wavefront.
// SMEM: Usp 32x514 float2 (own layer's U slice) + Hs 16x514 float2
// (own layer's staged h rows) = 192.75KB.
// Warp tile: 8b x 8c (2 outputs per thread along c, +4 apart) -> W1T/h0 L2
// re-fetch bounded at ~512KB/CTA/wavefront.
// ---------------------------------------------------------------------------
#define USP_STRIDE 514
#define HS_STRIDE 514
#define SMEM_BYTES ((32 * USP_STRIDE + 16 * HS_STRIDE) * (int)sizeof(float2))

__global__ __launch_bounds__(256, 1) void fused_rnn(
    const float* __restrict__ U0, const float* __restrict__ U1,
    const float* __restrict__ bias, float* __restrict__ out)
{
    extern __shared__ __align__(16) float2 smem[];
    float2* Usp = smem;                       // [32][USP_STRIDE]
    float2* Hs = smem + 32 * USP_STRIDE;      // [16][HS_STRIDE]

    const int tid = threadIdx.x;
    const int bid = blockIdx.x;
    const int layer = bid >> 6;               // 0 or 1
    const int grp = (bid >> 5) & 1;           // 0 or 1 (16 b-rows)
    const int c0 = (bid & 31) * 32;
    const int b0 = grp * 16;

    unsigned* cnt = &g_cnt[grp * 32];

    // Stage own layer's U slice, paired: Usp[c][j] = (U[j][c0+c], U[j+512][c0+c])
    const float* U = layer ? U1 : U0;
    for (int i = tid; i < 32 * 512; i += 256) {
        int c = i & 31;
        int j = i >> 5;
        float2 pr;
        pr.x = U[(size_t)j * DSZ + c0 + c];
        pr.y = U[(size_t)(j + 512) * DSZ + c0 + c];
        Usp[c * USP_STRIDE + j] = pr;
    }
    __syncthreads();

    // Warp tile: 8 warps = 2 b-halves x 4 c-quarters; thread owns (b, cA), (b, cB=cA+4)
    const int w_ = tid >> 5;
    const int lane = tid & 31;
    const int wr = w_ >> 2;                   // 0..1
    const int wc = w_ & 3;                    // 0..3
    const int b_l = wr * 8 + (lane >> 2);     // 0..15
    const int cl = wc * 8 + (lane & 3);       // 0..31 (base)
    const int clB = cl + 4;
    const int b = b0 + b_l;
    const int cA = c0 + cl;
    const int cB = c0 + clB;

    const float bvA = bias[layer * DSZ + cA];
    const float bvB = bias[layer * DSZ + cB];
    const int jjA = cA & 511, jjB = cB & 511;
    const int chi = cA >> 9;                  // uniform per CTA

    const ulonglong2* sh = (const ulonglong2*)(Hs + b_l * HS_STRIDE);
    const ulonglong2* suA = (const ulonglong2*)(Usp + cl * USP_STRIDE);
    const ulonglong2* suB = (const ulonglong2*)(Usp + clB * USP_STRIDE);
    const ulonglong2* gwA = (const ulonglong2*)&g_w1t[cA][0];
    const ulonglong2* gwB = (const ulonglong2*)&g_w1t[cB][0];

    for (int w = 0; w <= SSZ; ++w) {
        if (layer == 0 && w == SSZ) break;

        // Wait for wavefront w-1 complete in this group (64 arrivals each).
        if (w > 0) {
            if (tid == 0) {
                unsigned want = 64u * (unsigned)w;
                unsigned v;
                do {
                    asm volatile("ld.acquire.gpu.u32 %0, [%1];"
                                 : "=r"(v) : "l"(cnt) : "memory");
                } while (v < want);
            }
            __syncthreads();
        }

        if (layer == 0) {
            // ---- compute h0_w ----
            if (w > 0) {
                // stage h0_{w-1}: 16 paired rows (64KB) into Hs
                const ulonglong2* src =
                    (const ulonglong2*)&g_hp0[(w - 1) & 1][b0][0];
#pragma unroll
                for (int s = 0; s < 16; s++) {
                    int g = tid + s * 256;          // 0..4095
                    ulonglong2 v = __ldcg(src + g);
                    int r = g >> 8, q2 = g & 255;
                    *(ulonglong2*)(Hs + r * HS_STRIDE + q2 * 2) = v;
                }
                __syncthreads();
            }
            float zA = __ldcg(&g_buf0[((size_t)w * BSZ + b) * DSZ + cA]);
            float zB = __ldcg(&g_buf0[((size_t)w * BSZ + b) * DSZ + cB]);
            float sA = 0.f, sB = 0.f;
            if (w > 0) {
                ull aA = 0, aB = 0;
#pragma unroll 8
                for (int q = 0; q < 256; q++) {
                    ulonglong2 hv = sh[q];
                    ulonglong2 uA = suA[q];
                    ulonglong2 uB = suB[q];
                    aA = fma2(hv.x, uA.x, aA);
                    aA = fma2(hv.y, uA.y, aA);
                    aB = fma2(hv.x, uB.x, aB);
                    aB = fma2(hv.y, uB.y, aB);
                }
                float lo, hi;
                unpack2(aA, lo, hi); sA = __fadd_rn(lo, hi);
                unpack2(aB, lo, hi); sB = __fadd_rn(lo, hi);
            }
            float hA = xla_tanh(__fadd_rn(__fadd_rn(zA, sA), bvA));
            float hB = xla_tanh(__fadd_rn(__fadd_rn(zB, sB), bvB));
            ((float*)&g_hp0[w & 1][b][jjA])[chi] = hA;
            ((float*)&g_hp0[w & 1][b][jjB])[chi] = hB;
        } else if (w >= 1) {
            // ---- compute h1_t, t = w-1 ----
            const int t = w - 1;
            if (t > 0) {
                // stage h1_{t-1}: 16 paired rows into Hs
                const ulonglong2* src =
                    (const ulonglong2*)&g_hp1[(t - 1) & 1][b0][0];
#pragma unroll
                for (int s = 0; s < 16; s++) {
                    int g = tid + s * 256;
                    ulonglong2 v = __ldcg(src + g);
                    int r = g >> 8, q2 = g & 255;
                    *(ulonglong2*)(Hs + r * HS_STRIDE + q2 * 2) = v;
                }
                __syncthreads();
            }
            const ulonglong2* gh = (const ulonglong2*)&g_hp0[t & 1][b][0];

            float zW1A, zW1B, rU1A = 0.f, rU1B = 0.f;
            ull aWA = 0, aWB = 0;
            if (t > 0) {
                ull aUA = 0, aUB = 0;
                // depth-4 prefetch on 3 global streams; SMEM direct.
                ulonglong2 bh[4], bwA[4], bwB[4];
#pragma unroll
                for (int p = 0; p < 4; p++) {
                    bh[p] = __ldcg(gh + p);
                    bwA[p] = __ldcg(gwA + p);
                    bwB[p] = __ldcg(gwB + p);
                }
#pragma unroll 8
                for (int q = 0; q < 256; q++) {
                    const int sl = q & 3;
                    ulonglong2 hv = bh[sl], wAv = bwA[sl], wBv = bwB[sl];
                    if (q < 252) {
                        bh[sl] = __ldcg(gh + q + 4);
                        bwA[sl] = __ldcg(gwA + q + 4);
                        bwB[sl] = __ldcg(gwB + q + 4);
                    }
                    ulonglong2 h1v = sh[q];
                    ulonglong2 uAv = suA[q];
                    ulonglong2 uBv = suB[q];
                    aWA = fma2(hv.x, wAv.x, aWA);
                    aWA = fma2(hv.y, wAv.y, aWA);
                    aWB = fma2(hv.x, wBv.x, aWB);
                    aWB = fma2(hv.y, wBv.y, aWB);
                    aUA = fma2(h1v.x, uAv.x, aUA);
                    aUA = fma2(h1v.y, uAv.y, aUA);
                    aUB = fma2(h1v.x, uBv.x, aUB);
                    aUB = fma2(h1v.y, uBv.y, aUB);
                }
                float lo, hi;
                unpack2(aUA, lo, hi); rU1A = __fadd_rn(lo, hi);
                unpack2(aUB, lo, hi); rU1B = __fadd_rn(lo, hi);
            } else {
                ulonglong2 bh[4], bwA[4], bwB[4];
#pragma unroll
                for (int p = 0; p < 4; p++) {
                    bh[p] = __ldcg(gh + p);
                    bwA[p] = __ldcg(gwA + p);
                    bwB[p] = __ldcg(gwB + p);
                }
#pragma unroll 8
                for (int q = 0; q < 256; q++) {
                    const int sl = q & 3;
                    ulonglong2 hv = bh[sl], wAv = bwA[sl], wBv = bwB[sl];
                    if (q < 252) {
                        bh[sl] = __ldcg(gh + q + 4);
                        bwA[sl] = __ldcg(gwA + q + 4);
                        bwB[sl] = __ldcg(gwB + q + 4);
                    }
                    aWA = fma2(hv.x, wAv.x, aWA);
                    aWA = fma2(hv.y, wAv.y, aWA);
                    aWB = fma2(hv.x, wBv.x, aWB);
                    aWB = fma2(hv.y, wBv.y, aWB);
                }
            }
            {
                float lo, hi;
                unpack2(aWA, lo, hi); zW1A = __fadd_rn(lo, hi);
                unpack2(aWB, lo, hi); zW1B = __fadd_rn(lo, hi);
            }
            // z = ((h0@W1) + (h1_prev@U1)) + b1  — validated order
            float hA = xla_tanh(__fadd_rn(__fadd_rn(zW1A, rU1A), bvA));
            float hB = xla_tanh(__fadd_rn(__fadd_rn(zW1B, rU1B), bvB));
            // final output [B][S][D]
            out[((size_t)b * SSZ + t) * DSZ + cA] = hA;
            out[((size_t)b * SSZ + t) * DSZ + cB] = hB;
            // paired for next wavefront's rU1
            ((float*)&g_hp1[t & 1][b][jjA])[chi] = hA;
            ((float*)&g_hp1[t & 1][b][jjB])[chi] = hB;
        }

        // Arrive (release) — end of wavefront w. Skip at final wavefront.
        if (w < SSZ) {
            __syncthreads();
            if (tid == 0) {
                asm volatile("red.release.gpu.global.add.u32 [%0], 1;"
                             :: "l"(cnt) : "memory");
            }
        }
    }

    // Cleanup: last of 128 CTAs restores barrier state for graph replay.
    __syncthreads();
    if (tid == 0) {
        __threadfence();
        unsigned prev = atomicAdd(&g_cleanup, 1u);
        if (prev == 127u) {
            g_cnt[0] = 0u;
            g_cnt[32] = 0u;
            g_cleanup = 0u;
            __threadfence();
        }
    }
}

// ---------------------------------------------------------------------------
// Launch: W1 transpose + Z0 GEMM, then single fused wavefront kernel.
// ---------------------------------------------------------------------------
extern "C" void kernel_launch(void* const* d_in, const int* in_sizes, int n_in,
                              void* d_out, int out_size)
{
    const float* x  = (const float*)d_in[0];   // [B,S,D]
    const float* Wh = (const float*)d_in[1];   // [L,D,D]
    const float* Uh = (const float*)d_in[2];   // [L,D,D]
    const float* bb = (const float*)d_in[3];   // [L,D]
    float* out = (float*)d_out;                // [B,S,D]

    const int DD = DSZ * DSZ;
    dim3 ggrid(DSZ / 64, (BSZ * SSZ) / 128);   // (16, 256)

    // Prep: W1 transposed+paired (4MB, one-time per launch)
    transpose_w1<<<(DSZ * (DSZ / 2)) / 256, 256>>>(Wh + DD);

    // Z0 = x @ W0 (remap rows to time-major), into g_buf0
    gemm_kernel<<<ggrid, 256>>>(x, /*a_sel=*/-1, Wh, /*c_sel=*/0, /*remap=*/1);

    // Fused two-layer wavefront scan (1025 wavefronts)
    cudaFuncSetAttribute(fused_rnn,
                         cudaFuncAttributeMaxDynamicSharedMemorySize,
                         SMEM_BYTES);
    fused_rnn<<<128, 256, SMEM_BYTES>>>(Uh, Uh + DD, bb, out);
}

// round 17
// speedup vs baseline: 2.8525x; 2.8525x over previous
#include <cuda_runtime.h>
#include <math.h>

// Problem constants
#define BSZ 32
#define SSZ 1024
#define DSZ 1024

typedef unsigned long long ull;

// Scratch buffers (device globals — no allocation allowed in kernel_launch).
// g_buf0: Z0 (time-major [S][B][D]) -> later overwritten with Z1 by GEMM1.
__device__ float g_buf0[(size_t)BSZ * SSZ * DSZ];
// Full paired h0 history: g_h0p[t*B + b][j] = (h0[b][j], h0[b][j+512]).
// Row index m = t*32 + b matches GEMM1's A row (time-major).
__device__ float2 g_h0p[(size_t)BSZ * SSZ][DSZ / 2];
// Layer-1 paired h state, double-buffered by parity.
__device__ float2 g_hp1[2][BSZ][DSZ / 2];

// Monotonic per-b-group barrier counters (4 groups, separate 128B lines)
// + cleanup counter. Zero-init; restored at launch end.
__device__ unsigned g_cnt[4 * 32];
__device__ unsigned g_cleanup;

// ---------------------------------------------------------------------------
// Packed f32x2 helpers (sm_100+). Each lane is an independent IEEE fp32 FMA —
// bit-identical to two scalar fmaf chains.
// ---------------------------------------------------------------------------
__device__ __forceinline__ ull fma2(ull a, ull b, ull c) {
    ull d;
    asm("fma.rn.f32x2 %0, %1, %2, %3;" : "=l"(d) : "l"(a), "l"(b), "l"(c));
    return d;
}
__device__ __forceinline__ void unpack2(ull v, float& lo, float& hi) {
    asm("mov.b64 {%0, %1}, %2;" : "=f"(lo), "=f"(hi) : "l"(v));
}
__device__ __forceinline__ ull pack2(float lo, float hi) {
    ull r;
    asm("mov.b64 %0, {%1, %2};" : "=l"(r) : "f"(lo), "f"(hi));
    return r;
}

// ---------------------------------------------------------------------------
// Reference arithmetic (validated bit-exact rounds 9-15):
//   dot  = split-K=2: two ascending fp32 fmaf chains of 512, combined s0+s1
//   z    = (inp@W + h_prev@U) + b  (rn adds, that order)
//   tanh = XLA fast-tanh with_fma: clamp +-7.99881172180175781, FMA Horner,
//          rn divide, |x|<0.0004 passthrough.
// ---------------------------------------------------------------------------
__device__ __forceinline__ float xla_tanh(float x) {
    const float kMax = 7.99881172180175781f;
    float ax = fabsf(x);
    float xc = fminf(fmaxf(x, -kMax), kMax);
    float x2 = __fmul_rn(xc, xc);
    float p = -2.76076847742355e-16f;
    p = fmaf(x2, p, 2.00018790482477e-13f);
    p = fmaf(x2, p, -8.60467152213735e-11f);
    p = fmaf(x2, p, 5.12229709037114e-08f);
    p = fmaf(x2, p, 1.48572235717979e-05f);
    p = fmaf(x2, p, 6.37261928875436e-04f);
    p = fmaf(x2, p, 4.89352455891786e-03f);
    p = __fmul_rn(xc, p);
    float q = 1.19825839466702e-06f;
    q = fmaf(x2, q, 1.18534705686654e-04f);
    q = fmaf(x2, q, 2.26843463243900e-03f);
    q = fmaf(x2, q, 4.89352518554385e-03f);
    float r = __fdiv_rn(p, q);
    return (ax < 0.0004f) ? x : r;
}

// ---------------------------------------------------------------------------
// FFMA2 GEMM: C(g_buf0) = A @ W. Split-K=2 chains in f32x2 lanes; final lo+hi.
//   a_paired=0: A = external fp32 [M][1024]; pairs built at SMEM-store time.
//   a_paired=1: A = g_h0p paired rows ([M][512] float2) — loaded directly.
//   remap=1: A row m = b*S + s  ->  C row = s*B + b   (x -> time-major Z0)
//   remap=0: C row = m
// ---------------------------------------------------------------------------
__global__ __launch_bounds__(256) void gemm_kernel(
    const float* __restrict__ A_ext, int a_paired,
    const float* __restrict__ W, int remap)
{
    const int N_ = DSZ, K_ = DSZ;
    float* C = g_buf0;

    __shared__ ull As2[8][132];   // [klo][m] pairs, padded row
    __shared__ ull Bs2[8][66];    // [klo][n] pairs, padded row

    const int tid = threadIdx.x;
    const int tx = tid & 15;
    const int ty = tid >> 4;
    const int m0 = blockIdx.y * 128;
    const int n0 = blockIdx.x * 64;

    ull acc2[8][4];
#pragma unroll
    for (int i = 0; i < 8; i++)
#pragma unroll
        for (int j = 0; j < 4; j++) acc2[i][j] = 0ull;

    const int arow = tid >> 1;             // 0..127
    const int akq = (tid & 1) * 4;         // 0 or 4
    const int brow = tid >> 4;             // 0..15 (use <8)
    const int bnq = (tid & 15) * 4;        // 0..60

    const ulonglong2* Ap = (const ulonglong2*)&g_h0p[0][0];  // row stride 256

    for (int kt = 0; kt < 512; kt += 8) {
        if (a_paired) {
            // direct paired loads: 2 x ulonglong2 = 4 pairs
            size_t base = (size_t)(m0 + arow) * 256 + ((kt + akq) >> 1);
            ulonglong2 p0 = Ap[base];
            ulonglong2 p1 = Ap[base + 1];
            As2[akq + 0][arow] = p0.x;
            As2[akq + 1][arow] = p0.y;
            As2[akq + 2][arow] = p1.x;
            As2[akq + 3][arow] = p1.y;
        } else {
            float4 lo = *(const float4*)&A_ext[(size_t)(m0 + arow) * K_ + kt + akq];
            float4 hi = *(const float4*)&A_ext[(size_t)(m0 + arow) * K_ + kt + 512 + akq];
            As2[akq + 0][arow] = pack2(lo.x, hi.x);
            As2[akq + 1][arow] = pack2(lo.y, hi.y);
            As2[akq + 2][arow] = pack2(lo.z, hi.z);
            As2[akq + 3][arow] = pack2(lo.w, hi.w);
        }
        if (tid < 128) {
            float4 blo = *(const float4*)&W[(size_t)(kt + brow) * N_ + n0 + bnq];
            float4 bhi = *(const float4*)&W[(size_t)(kt + 512 + brow) * N_ + n0 + bnq];
            Bs2[brow][bnq + 0] = pack2(blo.x, bhi.x);
            Bs2[brow][bnq + 1] = pack2(blo.y, bhi.y);
            Bs2[brow][bnq + 2] = pack2(blo.z, bhi.z);
            Bs2[brow][bnq + 3] = pack2(blo.w, bhi.w);
        }
        __syncthreads();

#pragma unroll
        for (int kk = 0; kk < 8; kk++) {
            ull a2[8], b2[4];
#pragma unroll
            for (int i = 0; i < 8; i++) a2[i] = As2[kk][ty * 8 + i];
#pragma unroll
            for (int j = 0; j < 4; j++) b2[j] = Bs2[kk][tx * 4 + j];
#pragma unroll
            for (int i = 0; i < 8; i++)
#pragma unroll
                for (int j = 0; j < 4; j++)
                    acc2[i][j] = fma2(a2[i], b2[j], acc2[i][j]);
        }
        __syncthreads();
    }

#pragma unroll
    for (int i = 0; i < 8; i++) {
        int m = m0 + ty * 8 + i;
        int orow = remap ? ((m & (SSZ - 1)) * BSZ + (m >> 10)) : m;
        float lo, hi;
        float4 v;
        unpack2(acc2[i][0], lo, hi); v.x = __fadd_rn(lo, hi);
        unpack2(acc2[i][1], lo, hi); v.y = __fadd_rn(lo, hi);
        unpack2(acc2[i][2], lo, hi); v.z = __fadd_rn(lo, hi);
        unpack2(acc2[i][3], lo, hi); v.w = __fadd_rn(lo, hi);
        *(float4*)&C[(size_t)orow * N_ + n0 + tx * 4] = v;
    }
}

// ---------------------------------------------------------------------------
// Persistent recurrent kernel (R13 structure + overhead trims).
// Grid = 128 CTAs = 4 b-groups x 32 c-groups; CTA covers b in [b0,b0+8),
// c in [c0,c0+32); 256 threads, 1 output (b, c)/thread.
// layer=0: Z=g_buf0(Z0), h stored ONLY paired into g_h0p[t*B+b] (full history,
//          consumed directly by GEMM1). layer=1: Z=g_buf0(Z1), writes out +
//          paired double-buffered g_hp1.
// Barrier: per-group monotonic counter; arrive = red.release (orders prior
// stores), wait = ld.acquire poll for 32*t. Z_{t+1} prefetched before arrive.
// Dynamic SMEM: Usp 32x514 float2 + Hs 8x514 float2 = 164.5KB.
// ---------------------------------------------------------------------------
#define USP_STRIDE 514
#define HS_STRIDE 514
#define SMEM_BYTES ((32 * USP_STRIDE + 8 * HS_STRIDE) * (int)sizeof(float2))

__global__ __launch_bounds__(256, 1) void rnn_kernel(
    int layer, const float* __restrict__ U, const float* __restrict__ bias,
    float* __restrict__ out)
{
    extern __shared__ __align__(16) float2 smem[];
    float2* Usp = smem;                      // [32][USP_STRIDE]
    float2* Hs = smem + 32 * USP_STRIDE;     // [8][HS_STRIDE]

    const int tid = threadIdx.x;
    const int bid = blockIdx.x;
    const int grp = bid >> 5;                // 0..3
    const int b0 = grp * 8;
    const int c0 = (bid & 31) * 32;

    unsigned* cnt = &g_cnt[grp * 32];

    // Stage paired U slice: Usp[c][j] = (U[j][c0+c], U[j+512][c0+c])
    for (int i = tid; i < 32 * 512; i += 256) {
        int c = i & 31;
        int j = i >> 5;
        float2 pr;
        pr.x = U[(size_t)j * DSZ + c0 + c];
        pr.y = U[(size_t)(j + 512) * DSZ + c0 + c];
        Usp[c * USP_STRIDE + j] = pr;
    }
    __syncthreads();

    const int w_ = tid >> 5;
    const int lane = tid & 31;
    const int b_l = (w_ >> 2) * 4 + (lane >> 3);  // 0..7
    const int c_l = (w_ & 3) * 8 + (lane & 7);    // 0..31
    const int b = b0 + b_l;
    const int cg = c0 + c_l;

    const float bval = bias[cg];
    const int jj = cg & 511;
    const int chi = cg >> 9;                 // uniform per CTA

    const ulonglong2* hrow = (const ulonglong2*)(Hs + b_l * HS_STRIDE);
    const ulonglong2* urow = (const ulonglong2*)(Usp + c_l * USP_STRIDE);

    // Z prefetch for t = 0
    float znext = __ldcg(&g_buf0[(size_t)b * DSZ + cg]);

    for (int t = 0; t < SSZ; ++t) {
        if (t > 0) {
            // Wait for all 32 group CTAs to finish step t-1.
            if (tid == 0) {
                unsigned want = 32u * (unsigned)t;
                unsigned v;
                do {
                    asm volatile("ld.acquire.gpu.u32 %0, [%1];"
                                 : "=r"(v) : "l"(cnt) : "memory");
                } while (v < want);
            }
            __syncthreads();

            // Bulk load group's 8 paired h rows (32KB contiguous) into SMEM.
            const ulonglong2* src = layer
                ? (const ulonglong2*)&g_hp1[(t - 1) & 1][b0][0]
                : (const ulonglong2*)&g_h0p[(size_t)(t - 1) * BSZ + b0][0];
#pragma unroll
            for (int s = 0; s < 8; s++) {
                int g = tid + s * 256;            // 0..2047
                ulonglong2 v = __ldcg(src + g);
                int r = g >> 8, q2 = g & 255;
                *(ulonglong2*)(Hs + r * HS_STRIDE + q2 * 2) = v;
            }
            __syncthreads();
        }

        float zW = znext;
        float s_tot = 0.f;
        if (t > 0) {
            // 4-deep software pipeline; single ascending fma2 chain (bit-exact).
            ull s01 = 0;
            ulonglong2 hb[4], ub[4];
#pragma unroll
            for (int p = 0; p < 4; p++) { hb[p] = hrow[p]; ub[p] = urow[p]; }
#pragma unroll 8
            for (int q = 0; q < 256; q++) {
                const int slot = q & 3;
                ulonglong2 hv = hb[slot];
                ulonglong2 uv = ub[slot];
                if (q < 252) {
                    hb[slot] = hrow[q + 4];
                    ub[slot] = urow[q + 4];
                }
                s01 = fma2(hv.x, uv.x, s01);
                s01 = fma2(hv.y, uv.y, s01);
            }
            float s0, s1;
            unpack2(s01, s0, s1);
            s_tot = __fadd_rn(s0, s1);            // split-K combine p0 + p1
        }
        float z = __fadd_rn(__fadd_rn(zW, s_tot), bval);  // (dot1+dot2)+b
        float hv = xla_tanh(z);

        if (layer == 0) {
            // paired history only — GEMM1 consumes it directly
            ((float*)&g_h0p[(size_t)t * BSZ + b][jj])[chi] = hv;
        } else {
            out[((size_t)b * SSZ + t) * DSZ + cg] = hv;
            ((float*)&g_hp1[t & 1][b][jj])[chi] = hv;
        }

        if (t != SSZ - 1) {
            // Prefetch Z_{t+1} (recurrence-independent) — overlaps barrier.
            znext = __ldcg(&g_buf0[((size_t)(t + 1) * BSZ + b) * DSZ + cg]);
            __syncthreads();
            if (tid == 0) {
                // release-arrive: orders this CTA's h stores before the count.
                asm volatile("red.release.gpu.global.add.u32 [%0], 1;"
                             :: "l"(cnt) : "memory");
            }
        }
    }

    // Cleanup: last of 128 CTAs restores barrier state for graph replay.
    __syncthreads();
    if (tid == 0) {
        __threadfence();
        unsigned prev = atomicAdd(&g_cleanup, 1u);
        if (prev == 127u) {
            for (int g = 0; g < 4; g++) g_cnt[g * 32] = 0u;
            g_cleanup = 0u;
            __threadfence();
        }
    }
}

// ---------------------------------------------------------------------------
// Launch: Z0 = x@W0 -> scan layer0 (paired history) -> Z1 = h0@W1 (paired A)
//         -> scan layer1 -> out
// ---------------------------------------------------------------------------
extern "C" void kernel_launch(void* const* d_in, const int* in_sizes, int n_in,
                              void* d_out, int out_size)
{
    const float* x  = (const float*)d_in[0];   // [B,S,D]
    const float* Wh = (const float*)d_in[1];   // [L,D,D]
    const float* Uh = (const float*)d_in[2];   // [L,D,D]
    const float* bb = (const float*)d_in[3];   // [L,D]
    float* out = (float*)d_out;                // [B,S,D]

    const int DD = DSZ * DSZ;
    dim3 ggrid(DSZ / 64, (BSZ * SSZ) / 128);   // (16, 256)

    cudaFuncSetAttribute(rnn_kernel,
                         cudaFuncAttributeMaxDynamicSharedMemorySize,
                         SMEM_BYTES);

    // Layer 0: Z0 = x @ W0 (remap rows to time-major) -> g_buf0
    gemm_kernel<<<ggrid, 256>>>(x, /*a_paired=*/0, Wh, /*remap=*/1);

    // Layer 0 scan: h0_t = tanh((Z0_t + h0_{t-1}@U0) + b0) -> g_h0p (paired)
    rnn_kernel<<<128, 256, SMEM_BYTES>>>(/*layer=*/0, Uh, bb, nullptr);

    // Layer 1: Z1 = h0 @ W1 (A read directly from paired history) -> g_buf0
    gemm_kernel<<<ggrid, 256>>>(nullptr, /*a_paired=*/1, Wh + DD, /*remap=*/0);

    // Layer 1 scan: out_t = tanh((Z1_t + out_{t-1}@U1) + b1) -> d_out
    rnn_kernel<<<128, 256, SMEM_BYTES>>>(/*layer=*/1, Uh + DD, bb + DSZ, out);
}